// round 13
// baseline (speedup 1.0000x reference)
#include <cuda_runtime.h>
#include <cuda_fp16.h>
#include <math.h>
#include <stdint.h>

#define BB 4
#define CC 64
#define NN 4096
#define TQa 128
#define TKa 64
#define NTILE (NN / TKa)      // 64 tiles per batch
#define NSPLIT 2
#define TPS (NTILE / NSPLIT)  // 32 tiles per split

// Scratch (__device__ globals). K/V stored PRE-PACKED (fp16) in mma-fragment order.
__device__ float     g_wt[3 * CC * CC];         // [m][c][o] transposed weights
__device__ __half    g_qh[BB * NN * CC];        // (b, n, c) token-major fp16
__device__ uint32_t  g_kph[BB * NTILE * 2048];  // packed K tiles (half2 regs)
__device__ uint32_t  g_vph[BB * NTILE * 2048];  // packed V tiles
__device__ float     g_po[NSPLIT * BB * CC * NN];  // unnormalized O partials
__device__ float     g_pl[NSPLIT * BB * NN];       // row-sum partials

// ---------------------------------------------------------------------------
__device__ __forceinline__ float ex2(float x) {
    float y;
    asm("ex2.approx.ftz.f32 %0, %1;" : "=f"(y) : "f"(x));
    return y;
}
__device__ __forceinline__ uint32_t h2(float lo, float hi) {
    __half2 h = __floats2half2_rn(lo, hi);
    return *(uint32_t*)&h;
}
__device__ __forceinline__ uint32_t smem_u32(const void* p) {
    uint32_t a;
    asm("{ .reg .u64 t; cvta.to.shared.u64 t, %1; cvt.u32.u64 %0, t; }" : "=r"(a) : "l"(p));
    return a;
}
__device__ __forceinline__ void cp16(uint32_t dst, const void* src) {
    asm volatile("cp.async.cg.shared.global [%0], [%1], 16;" :: "r"(dst), "l"(src));
}
__device__ __forceinline__ void cp_commit() { asm volatile("cp.async.commit_group;"); }
__device__ __forceinline__ void cp_wait0() { asm volatile("cp.async.wait_group 0;"); }

// fp16 m16n8k16 mma, fp32 accumulate
__device__ __forceinline__ void mma16(float* d, const uint32_t* a,
                                      uint32_t b0, uint32_t b1) {
    asm volatile(
        "mma.sync.aligned.m16n8k16.row.col.f32.f16.f16.f32 "
        "{%0,%1,%2,%3}, {%4,%5,%6,%7}, {%8,%9}, {%0,%1,%2,%3};"
        : "+f"(d[0]), "+f"(d[1]), "+f"(d[2]), "+f"(d[3])
        : "r"(a[0]), "r"(a[1]), "r"(a[2]), "r"(a[3]), "r"(b0), "r"(b1));
}

// ---------------------------------------------------------------------------
// Kernel 0: transpose weights once: g_wt[m][c][o] = w_m[o][c]
// ---------------------------------------------------------------------------
__global__ void __launch_bounds__(256) wtrans_kernel(
    const float* __restrict__ wq, const float* __restrict__ wk,
    const float* __restrict__ wv)
{
    int i = blockIdx.x * 256 + threadIdx.x;   // 12288 total
    int m = i >> 12, rem = i & 4095;
    int o = rem >> 6, c = rem & 63;
    const float* w = (m == 0) ? wq : (m == 1) ? wk : wv;
    g_wt[m * 4096 + c * 64 + o] = w[o * 64 + c];  // coalesced read, scattered write
}

// ---------------------------------------------------------------------------
// Kernel 1: fused QKV projection. Weights staged via coalesced float4 from the
// pre-transposed g_wt. K/V packed (fp16 fragment order) via SMEM.
// SMEM: Xs[4096] | Ws[12288]  (Xs region reused for K/V repack)
// ---------------------------------------------------------------------------
__global__ void __launch_bounds__(256) proj_kernel(
    const float* __restrict__ x,
    const float* __restrict__ bq, const float* __restrict__ bk,
    const float* __restrict__ bv)
{
    extern __shared__ float sm[];
    float* Xs = sm;               // [C][64]
    float* Ws = sm + CC * 64;     // [3][C][64]  (c-major, o contiguous)

    const int b  = blockIdx.y;
    const int tile = blockIdx.x;
    const int n0 = tile * 64;
    const int tid = threadIdx.x;

    {
        int row = tid >> 2;
        int col = (tid & 3) * 16;
        const float* src = x + ((size_t)(b * CC + row) * NN + n0 + col);
        float* dst = Xs + row * 64 + col;
        #pragma unroll
        for (int k = 0; k < 16; k += 4)
            *(float4*)(dst + k) = *(const float4*)(src + k);
    }
    // Coalesced weight staging: 3072 float4 (12 per thread)
    #pragma unroll
    for (int r = 0; r < 12; r++) {
        int i4 = (tid + 256 * r) * 4;
        *(float4*)(Ws + i4) = *(const float4*)(g_wt + i4);
    }
    __syncthreads();

    const int ti = tid >> 4, tj = tid & 15;
    const int o0 = ti * 4, nn0 = tj * 4;

    float acc[3][4][4];
    #pragma unroll
    for (int m = 0; m < 3; m++)
        #pragma unroll
        for (int i = 0; i < 4; i++)
            #pragma unroll
            for (int j = 0; j < 4; j++) acc[m][i][j] = 0.f;

    #pragma unroll 4
    for (int c = 0; c < CC; c++) {
        float4 x4 = *(float4*)(Xs + c * 64 + nn0);
        float xv[4] = {x4.x, x4.y, x4.z, x4.w};
        #pragma unroll
        for (int m = 0; m < 3; m++) {
            float4 w4 = *(float4*)(Ws + (m * CC + c) * 64 + o0);
            float wv_[4] = {w4.x, w4.y, w4.z, w4.w};
            #pragma unroll
            for (int oo = 0; oo < 4; oo++)
                #pragma unroll
                for (int nn = 0; nn < 4; nn++)
                    acc[m][oo][nn] += wv_[oo] * xv[nn];
        }
    }

    float bqv[4], bkv[4], bvv[4];
    #pragma unroll
    for (int oo = 0; oo < 4; oo++) {
        bqv[oo] = bq[o0 + oo];
        bkv[oo] = bk[o0 + oo];
        bvv[oo] = bv[o0 + oo];
    }
    // Q token-major fp16 (channels o0,o0+1 / o0+2,o0+3 as half2)
    {
        uint32_t* q32 = (uint32_t*)g_qh;
        #pragma unroll
        for (int nn = 0; nn < 4; nn++) {
            int token = n0 + nn0 + nn;
            size_t base = (size_t)(b * NN + token) * (CC / 2) + (o0 >> 1);
            q32[base]     = h2(acc[0][0][nn] + bqv[0], acc[0][1][nn] + bqv[1]);
            q32[base + 1] = h2(acc[0][2][nn] + bqv[2], acc[0][3][nn] + bqv[3]);
        }
    }

    // K/V fragment packing through SMEM (reuse Xs region: 16 KB)
    __half* KPh = (__half*)sm;            // 4096 halves (8 KB)
    __half* VPh = (__half*)sm + 4096;     // 4096 halves
    __syncthreads();
    #pragma unroll
    for (int oo = 0; oo < 4; oo++) {
        int c = o0 + oo;
        #pragma unroll
        for (int nn = 0; nn < 4; nn++) {
            int j = nn0 + nn;
            {   // K: B-frag of MMA1 (k=channel, n=token)
                int s = c >> 4, t = j >> 3;
                int lamk = 4 * (j & 7) + ((c >> 1) & 3);
                int breg = (c >> 3) & 1;
                int u32i = ((s * 4 + (t >> 1)) * 32 + lamk) * 4 + (t & 1) * 2 + breg;
                KPh[u32i * 2 + (c & 1)] = __float2half_rn(acc[1][oo][nn] + bkv[oo]);
            }
            {   // V: B-frag of MMA2 (k=token, n=channel)
                int s = j >> 4, t = c >> 3;
                int lamv = 4 * (c & 7) + ((j >> 1) & 3);
                int breg = (j >> 3) & 1;
                int u32i = ((s * 4 + (t >> 1)) * 32 + lamv) * 4 + (t & 1) * 2 + breg;
                VPh[u32i * 2 + (j & 1)] = __float2half_rn(acc[2][oo][nn] + bvv[oo]);
            }
        }
    }
    __syncthreads();
    // Coalesced copy out (2048 u32 each = 512 uint4)
    {
        const uint4* ks = (const uint4*)KPh;
        const uint4* vs = (const uint4*)VPh;
        uint4* kdst = (uint4*)(g_kph + (size_t)(b * NTILE + tile) * 2048);
        uint4* vdst = (uint4*)(g_vph + (size_t)(b * NTILE + tile) * 2048);
        #pragma unroll
        for (int r = 0; r < 2; r++) {
            int i = tid + 256 * r;
            kdst[i] = ks[i];
            vdst[i] = vs[i];
        }
    }
}

// ---------------------------------------------------------------------------
// Kernel 2: fp16 m16n8k16 flash attention, split-KV, double-buffered cp.async.
// 4 warps x 32 query rows. Q frags in registers. P: C-frag == A-frag (cvt only).
// SMEM (u32): Kb[2][2048] | Vb[2][2048] = 32 KB
// ---------------------------------------------------------------------------
__global__ void __launch_bounds__(128, 2) attn_mma_kernel()
{
    extern __shared__ uint32_t smu[];
    uint32_t* Kb = smu;           // 2 x 2048
    uint32_t* Vb = smu + 4096;    // 2 x 2048

    const int b  = blockIdx.y;
    const int q0 = blockIdx.x * TQa;
    const int sp = blockIdx.z;
    const int tid = threadIdx.x, w = tid >> 5, lam = tid & 31;
    const int g = lam >> 2, tau = lam & 3;
    const uint32_t smK = smem_u32(Kb), smV = smem_u32(Vb);
    const float SC = 1.4426950408889634f / (float)NN;  // log2(e)/N

    // ---- Q A-fragments in registers: qa[m][s][0..3] ----
    uint32_t qa[2][4][4];
    {
        const uint32_t* q32 = (const uint32_t*)g_qh;
        #pragma unroll
        for (int m = 0; m < 2; m++) {
            size_t rg  = (size_t)(b * NN + q0 + w * 32 + m * 16 + g) * 32;
            size_t rg8 = rg + 8 * 32;
            #pragma unroll
            for (int s = 0; s < 4; s++) {
                qa[m][s][0] = q32[rg  + 8 * s + tau];
                qa[m][s][1] = q32[rg8 + 8 * s + tau];
                qa[m][s][2] = q32[rg  + 8 * s + tau + 4];
                qa[m][s][3] = q32[rg8 + 8 * s + tau + 4];
            }
        }
    }

    float of[2][8][4];
    #pragma unroll
    for (int m = 0; m < 2; m++)
        #pragma unroll
        for (int t = 0; t < 8; t++)
            #pragma unroll
            for (int c = 0; c < 4; c++) of[m][t][c] = 0.f;
    float lA[2] = {0.f, 0.f};
    float lB[2] = {0.f, 0.f};

    const uint32_t* kp = g_kph + ((size_t)b * NTILE + sp * TPS) * 2048;
    const uint32_t* vp = g_vph + ((size_t)b * NTILE + sp * TPS) * 2048;

    // prologue: tile 0 -> buffer 0
    #pragma unroll
    for (int r = 0; r < 4; r++) {
        int i = tid + 128 * r;
        cp16(smK + i * 16, kp + i * 4);
        cp16(smV + i * 16, vp + i * 4);
    }
    cp_commit();

    for (int kt = 0; kt < TPS; kt++) {
        cp_wait0();
        __syncthreads();
        if (kt + 1 < TPS) {
            uint32_t nbb = (uint32_t)((kt + 1) & 1) * 8192u;  // byte offset
            const uint32_t* ksrc = kp + (size_t)(kt + 1) * 2048;
            const uint32_t* vsrc = vp + (size_t)(kt + 1) * 2048;
            #pragma unroll
            for (int r = 0; r < 4; r++) {
                int i = tid + 128 * r;
                cp16(smK + nbb + i * 16, ksrc + i * 4);
                cp16(smV + nbb + i * 16, vsrc + i * 4);
            }
            cp_commit();
        }

        const uint4* Kp4 = (const uint4*)(Kb + (kt & 1) * 2048);
        const uint4* Vp4 = (const uint4*)(Vb + (kt & 1) * 2048);

        // ---- MMA1: S = Q K^T ----
        float sf[2][8][4];
        #pragma unroll
        for (int m = 0; m < 2; m++)
            #pragma unroll
            for (int t = 0; t < 8; t++)
                #pragma unroll
                for (int c = 0; c < 4; c++) sf[m][t][c] = 0.f;

        #pragma unroll
        for (int s = 0; s < 4; s++)
            #pragma unroll
            for (int tp = 0; tp < 4; tp++) {
                uint4 kb = Kp4[(s * 4 + tp) * 32 + lam];
                mma16(sf[0][2 * tp],     qa[0][s], kb.x, kb.y);
                mma16(sf[0][2 * tp + 1], qa[0][s], kb.z, kb.w);
                mma16(sf[1][2 * tp],     qa[1][s], kb.x, kb.y);
                mma16(sf[1][2 * tp + 1], qa[1][s], kb.z, kb.w);
            }

        // ---- softmax: P = exp2(S * SC); C-frag layout == A-frag layout ----
        float rs[2][2] = {{0.f, 0.f}, {0.f, 0.f}};
        #pragma unroll
        for (int m = 0; m < 2; m++)
            #pragma unroll
            for (int t = 0; t < 8; t++) {
                float e0 = ex2(sf[m][t][0] * SC);
                float e1 = ex2(sf[m][t][1] * SC);
                float e2 = ex2(sf[m][t][2] * SC);
                float e3 = ex2(sf[m][t][3] * SC);
                rs[m][0] += e0 + e1;
                rs[m][1] += e2 + e3;
                sf[m][t][0] = e0; sf[m][t][1] = e1;
                sf[m][t][2] = e2; sf[m][t][3] = e3;
            }
        #pragma unroll
        for (int m = 0; m < 2; m++) {
            float a = rs[m][0], bs = rs[m][1];
            a += __shfl_xor_sync(0xffffffffu, a, 1);
            a += __shfl_xor_sync(0xffffffffu, a, 2);
            bs += __shfl_xor_sync(0xffffffffu, bs, 1);
            bs += __shfl_xor_sync(0xffffffffu, bs, 2);
            lA[m] += a;
            lB[m] += bs;
        }

        // P A-fragments: pure cvt
        uint32_t pa[2][4][4];
        #pragma unroll
        for (int m = 0; m < 2; m++)
            #pragma unroll
            for (int s = 0; s < 4; s++) {
                pa[m][s][0] = h2(sf[m][2 * s][0],     sf[m][2 * s][1]);
                pa[m][s][1] = h2(sf[m][2 * s][2],     sf[m][2 * s][3]);
                pa[m][s][2] = h2(sf[m][2 * s + 1][0], sf[m][2 * s + 1][1]);
                pa[m][s][3] = h2(sf[m][2 * s + 1][2], sf[m][2 * s + 1][3]);
            }

        // ---- MMA2: O += P V ----
        #pragma unroll
        for (int s = 0; s < 4; s++)
            #pragma unroll
            for (int tp = 0; tp < 4; tp++) {
                uint4 vb = Vp4[(s * 4 + tp) * 32 + lam];
                mma16(of[0][2 * tp],     pa[0][s], vb.x, vb.y);
                mma16(of[0][2 * tp + 1], pa[0][s], vb.z, vb.w);
                mma16(of[1][2 * tp],     pa[1][s], vb.x, vb.y);
                mma16(of[1][2 * tp + 1], pa[1][s], vb.z, vb.w);
            }
    }

    // ---- epilogue: unnormalized partials + row sums ----
    float* po = g_po + (size_t)(sp * BB + b) * CC * NN;
    float* pl = g_pl + (size_t)(sp * BB + b) * NN;
    #pragma unroll
    for (int m = 0; m < 2; m++)
        #pragma unroll
        for (int t = 0; t < 8; t++) {
            int rowa = q0 + w * 32 + m * 16 + g;
            int col = 8 * t + 2 * tau;
            po[(size_t)col       * NN + rowa]     = of[m][t][0];
            po[(size_t)(col + 1) * NN + rowa]     = of[m][t][1];
            po[(size_t)col       * NN + rowa + 8] = of[m][t][2];
            po[(size_t)(col + 1) * NN + rowa + 8] = of[m][t][3];
        }
    if (tau == 0) {
        #pragma unroll
        for (int m = 0; m < 2; m++) {
            int rowa = q0 + w * 32 + m * 16 + g;
            pl[rowa]     = lA[m];
            pl[rowa + 8] = lB[m];
        }
    }
}

// ---------------------------------------------------------------------------
// Kernel 3: combine partials: out = (O0 + O1) / (l0 + l1)
// ---------------------------------------------------------------------------
__global__ void __launch_bounds__(256) combine_kernel(float* __restrict__ out)
{
    int idx = blockIdx.x * 256 + threadIdx.x;      // float4 index over B*C*N/4
    int n = (idx * 4) & (NN - 1);
    int b = (idx * 4) >> 18;                       // / (CC*NN)
    float4 a = ((const float4*)g_po)[idx];
    float4 c = ((const float4*)g_po)[BB * CC * NN / 4 + idx];
    const float* l0 = g_pl + (size_t)b * NN + n;
    const float* l1 = g_pl + (size_t)(BB + b) * NN + n;
    float4 o;
    o.x = (a.x + c.x) / (l0[0] + l1[0]);
    o.y = (a.y + c.y) / (l0[1] + l1[1]);
    o.z = (a.z + c.z) / (l0[2] + l1[2]);
    o.w = (a.w + c.w) / (l0[3] + l1[3]);
    ((float4*)out)[idx] = o;
}

// ---------------------------------------------------------------------------
extern "C" void kernel_launch(void* const* d_in, const int* in_sizes, int n_in,
                              void* d_out, int out_size)
{
    const float* x  = (const float*)d_in[0];
    const float* wq = (const float*)d_in[1];
    const float* bq = (const float*)d_in[2];
    const float* wk = (const float*)d_in[3];
    const float* bk = (const float*)d_in[4];
    const float* wv = (const float*)d_in[5];
    const float* bv = (const float*)d_in[6];
    float* out = (float*)d_out;

    const int smem_proj = (CC * 64 + 3 * CC * 64) * sizeof(float);  // 65536 B
    const int smem_attn = (4096 + 4096) * sizeof(uint32_t);         // 32768 B
    cudaFuncSetAttribute(proj_kernel, cudaFuncAttributeMaxDynamicSharedMemorySize, smem_proj);
    cudaFuncSetAttribute(attn_mma_kernel, cudaFuncAttributeMaxDynamicSharedMemorySize, smem_attn);

    wtrans_kernel<<<48, 256>>>(wq, wk, wv);
    dim3 gp(NN / 64, BB);
    proj_kernel<<<gp, 256, smem_proj>>>(x, bq, bk, bv);
    dim3 ga(NN / TQa, BB, NSPLIT);
    attn_mma_kernel<<<ga, 128, smem_attn>>>();
    combine_kernel<<<BB * CC * NN / 4 / 256, 256>>>(out);
}

// round 15
// speedup vs baseline: 1.1323x; 1.1323x over previous
#include <cuda_runtime.h>
#include <cuda_fp16.h>
#include <math.h>
#include <stdint.h>

#define BB 4
#define CC 64
#define NN 4096
#define TQa 128
#define TKa 64
#define NTILE (NN / TKa)      // 64 tiles per batch
#define NSPLIT 2
#define TPS (NTILE / NSPLIT)  // 32 tiles per split

// Scratch (__device__ globals). Everything fp16 fragment-packed.
__device__ uint32_t  g_wph[3 * 2048];           // wq/wk/wv in K-tile B-frag layout
__device__ __half    g_qh[BB * NN * CC];        // (b, n, c) token-major fp16
__device__ uint32_t  g_kph[BB * NTILE * 2048];  // packed K tiles (half2 regs)
__device__ uint32_t  g_vph[BB * NTILE * 2048];  // packed V tiles
__device__ float     g_po[NSPLIT * BB * CC * NN];  // unnormalized O partials
__device__ float     g_pl[NSPLIT * BB * NN];       // row-sum partials

// ---------------------------------------------------------------------------
__device__ __forceinline__ float ex2(float x) {
    float y;
    asm("ex2.approx.ftz.f32 %0, %1;" : "=f"(y) : "f"(x));
    return y;
}
__device__ __forceinline__ uint32_t h2(float lo, float hi) {
    __half2 h = __floats2half2_rn(lo, hi);
    return *(uint32_t*)&h;
}
__device__ __forceinline__ uint32_t smem_u32(const void* p) {
    uint32_t a;
    asm("{ .reg .u64 t; cvta.to.shared.u64 t, %1; cvt.u32.u64 %0, t; }" : "=r"(a) : "l"(p));
    return a;
}
__device__ __forceinline__ void cp16(uint32_t dst, const void* src) {
    asm volatile("cp.async.cg.shared.global [%0], [%1], 16;" :: "r"(dst), "l"(src));
}
__device__ __forceinline__ void cp_commit() { asm volatile("cp.async.commit_group;"); }
__device__ __forceinline__ void cp_wait0() { asm volatile("cp.async.wait_group 0;"); }

// fp16 m16n8k16 mma, fp32 accumulate
__device__ __forceinline__ void mma16(float* d, const uint32_t* a,
                                      uint32_t b0, uint32_t b1) {
    asm volatile(
        "mma.sync.aligned.m16n8k16.row.col.f32.f16.f16.f32 "
        "{%0,%1,%2,%3}, {%4,%5,%6,%7}, {%8,%9}, {%0,%1,%2,%3};"
        : "+f"(d[0]), "+f"(d[1]), "+f"(d[2]), "+f"(d[3])
        : "r"(a[0]), "r"(a[1]), "r"(a[2]), "r"(a[3]), "r"(b0), "r"(b1));
}

// ---------------------------------------------------------------------------
// Kernel 0: pack weights once into B-frag layout (n = out-ch o, k = in-ch c).
// Identical index formula to the (passing) K-tile packing with j := o.
// ---------------------------------------------------------------------------
__global__ void __launch_bounds__(256) wpack_kernel(
    const float* __restrict__ wq, const float* __restrict__ wk,
    const float* __restrict__ wv)
{
    int i = blockIdx.x * 256 + threadIdx.x;   // 12288 total
    int m = i >> 12, rem = i & 4095;
    int o = rem >> 6, c = rem & 63;
    const float* w = (m == 0) ? wq : (m == 1) ? wk : wv;
    int s = c >> 4, t = o >> 3;
    int lamk = 4 * (o & 7) + ((c >> 1) & 3);
    int breg = (c >> 3) & 1;
    int u32i = ((s * 4 + (t >> 1)) * 32 + lamk) * 4 + (t & 1) * 2 + breg;
    ((__half*)g_wph)[m * 4096 + u32i * 2 + (c & 1)] = __float2half_rn(w[o * 64 + c]);
}

// ---------------------------------------------------------------------------
// Kernel 1: tensor-core QKV projection. 128 threads, warp = 16 tokens.
// SMEM (u32): Xh[2048] (token-major half2) | Wp[6144]  = 32 KB
// Repack buffers reuse Xh + first part of Wp after the MMAs.
// ---------------------------------------------------------------------------
__global__ void __launch_bounds__(128) proj_kernel(
    const float* __restrict__ x,
    const float* __restrict__ bq, const float* __restrict__ bk,
    const float* __restrict__ bv)
{
    extern __shared__ uint32_t smu[];
    uint32_t* Xh = smu;           // 2048 u32
    uint32_t* Wp = smu + 2048;    // 6144 u32
    const uint32_t smW = smem_u32(Wp);

    const int b = blockIdx.y, tile = blockIdx.x, n0 = tile * 64;
    const int tid = threadIdx.x, w = tid >> 5, lam = tid & 31;
    const int g = lam >> 2, tau = lam & 3;

    // stage packed weights (24 KB = 1536 uint4)
    #pragma unroll
    for (int r = 0; r < 12; r++) {
        int i = tid + 128 * r;
        cp16(smW + i * 16, (const uint4*)g_wph + i);
    }
    cp_commit();

    // stage X -> fp16 token-major SMEM
    __half* Xsh = (__half*)Xh;
    #pragma unroll
    for (int r = 0; r < 8; r++) {
        int idx4 = tid + 128 * r;           // 1024 float4
        int c = idx4 >> 4, j4 = (idx4 & 15) * 4;
        float4 v = *(const float4*)(x + (size_t)(b * CC + c) * NN + n0 + j4);
        Xsh[(j4 + 0) * 64 + c] = __float2half_rn(v.x);
        Xsh[(j4 + 1) * 64 + c] = __float2half_rn(v.y);
        Xsh[(j4 + 2) * 64 + c] = __float2half_rn(v.z);
        Xsh[(j4 + 3) * 64 + c] = __float2half_rn(v.w);
    }
    cp_wait0();
    __syncthreads();

    // A-fragments for token rows w*16+g, +8 (same pattern as attn Q loads)
    uint32_t xa[4][4];
    {
        int row = w * 16 + g;
        #pragma unroll
        for (int s = 0; s < 4; s++) {
            xa[s][0] = Xh[row * 32 + 8 * s + tau];
            xa[s][1] = Xh[(row + 8) * 32 + 8 * s + tau];
            xa[s][2] = Xh[row * 32 + 8 * s + tau + 4];
            xa[s][3] = Xh[(row + 8) * 32 + 8 * s + tau + 4];
        }
    }

    float acc[3][8][4];
    #pragma unroll
    for (int m = 0; m < 3; m++)
        #pragma unroll
        for (int t = 0; t < 8; t++)
            #pragma unroll
            for (int c = 0; c < 4; c++) acc[m][t][c] = 0.f;

    const uint4* Wp4 = (const uint4*)Wp;
    #pragma unroll
    for (int s = 0; s < 4; s++)
        #pragma unroll
        for (int m = 0; m < 3; m++)
            #pragma unroll
            for (int tp = 0; tp < 4; tp++) {
                uint4 kb = Wp4[m * 512 + (s * 4 + tp) * 32 + lam];
                mma16(acc[m][2 * tp],     xa[s], kb.x, kb.y);
                mma16(acc[m][2 * tp + 1], xa[s], kb.z, kb.w);
            }
    __syncthreads();  // done reading Xh / Wp

    // ---- Q: token-major fp16 global (C-frag cols 8t+2tau are one half2) ----
    {
        uint32_t* q32 = (uint32_t*)g_qh;
        size_t r0 = (size_t)(b * NN + n0 + w * 16 + g) * 32;
        size_t r8 = r0 + 8 * 32;
        #pragma unroll
        for (int t = 0; t < 8; t++) {
            float2 bb = *(const float2*)(bq + 8 * t + 2 * tau);
            q32[r0 + 4 * t + tau] = h2(acc[0][t][0] + bb.x, acc[0][t][1] + bb.y);
            q32[r8 + 4 * t + tau] = h2(acc[0][t][2] + bb.x, acc[0][t][3] + bb.y);
        }
    }

    // ---- K/V repack into SMEM, then coalesced copy out ----
    uint32_t* KPu = smu;                       // 2048 u32
    __half*  VPh  = (__half*)(smu + 2048);     // 2048 u32 region
    #pragma unroll
    for (int t = 0; t < 8; t++) {
        // K (n=token j, k=channel c): pair (c0,c1) shares one u32
        float2 bk2 = *(const float2*)(bk + 8 * t + 2 * tau);
        int kbase = (((t >> 1) * 4 + w) * 32 + 4 * g + tau) * 4 + (t & 1);
        KPu[kbase + 0] = h2(acc[1][t][0] + bk2.x, acc[1][t][1] + bk2.y);  // row r
        KPu[kbase + 2] = h2(acc[1][t][2] + bk2.x, acc[1][t][3] + bk2.y);  // row r+8
        // V (n=channel c, k=token j): scattered half writes
        float2 bv2 = *(const float2*)(bv + 8 * t + 2 * tau);
        int lam0 = 8 * tau + ((g >> 1) & 3);
        int ua = ((w * 4 + (t >> 1)) * 32 + lam0) * 4 + (t & 1) * 2;
        int hsel = g & 1;
        VPh[(ua +  0) * 2 + hsel] = __float2half_rn(acc[2][t][0] + bv2.x);  // c0, r
        VPh[(ua + 16) * 2 + hsel] = __float2half_rn(acc[2][t][1] + bv2.y);  // c1, r
        VPh[(ua +  1) * 2 + hsel] = __float2half_rn(acc[2][t][2] + bv2.x);  // c0, r+8
        VPh[(ua + 17) * 2 + hsel] = __float2half_rn(acc[2][t][3] + bv2.y);  // c1, r+8
    }
    __syncthreads();
    {
        const uint4* ks = (const uint4*)KPu;
        const uint4* vs = (const uint4*)VPh;
        uint4* kdst = (uint4*)(g_kph + (size_t)(b * NTILE + tile) * 2048);
        uint4* vdst = (uint4*)(g_vph + (size_t)(b * NTILE + tile) * 2048);
        #pragma unroll
        for (int r = 0; r < 4; r++) {
            int i = tid + 128 * r;
            kdst[i] = ks[i];
            vdst[i] = vs[i];
        }
    }
}

// ---------------------------------------------------------------------------
// Kernel 2: fp16 m16n8k16 flash attention, split-KV, double-buffered cp.async.
// (unchanged from round 11's passing version)
// SMEM (u32): Kb[2][2048] | Vb[2][2048] = 32 KB
// ---------------------------------------------------------------------------
__global__ void __launch_bounds__(128, 2) attn_mma_kernel()
{
    extern __shared__ uint32_t smu[];
    uint32_t* Kb = smu;           // 2 x 2048
    uint32_t* Vb = smu + 4096;    // 2 x 2048

    const int b  = blockIdx.y;
    const int q0 = blockIdx.x * TQa;
    const int sp = blockIdx.z;
    const int tid = threadIdx.x, w = tid >> 5, lam = tid & 31;
    const int g = lam >> 2, tau = lam & 3;
    const uint32_t smK = smem_u32(Kb), smV = smem_u32(Vb);
    const float SC = 1.4426950408889634f / (float)NN;  // log2(e)/N

    // ---- Q A-fragments in registers ----
    uint32_t qa[2][4][4];
    {
        const uint32_t* q32 = (const uint32_t*)g_qh;
        #pragma unroll
        for (int m = 0; m < 2; m++) {
            size_t rg  = (size_t)(b * NN + q0 + w * 32 + m * 16 + g) * 32;
            size_t rg8 = rg + 8 * 32;
            #pragma unroll
            for (int s = 0; s < 4; s++) {
                qa[m][s][0] = q32[rg  + 8 * s + tau];
                qa[m][s][1] = q32[rg8 + 8 * s + tau];
                qa[m][s][2] = q32[rg  + 8 * s + tau + 4];
                qa[m][s][3] = q32[rg8 + 8 * s + tau + 4];
            }
        }
    }

    float of[2][8][4];
    #pragma unroll
    for (int m = 0; m < 2; m++)
        #pragma unroll
        for (int t = 0; t < 8; t++)
            #pragma unroll
            for (int c = 0; c < 4; c++) of[m][t][c] = 0.f;
    float lA[2] = {0.f, 0.f};
    float lB[2] = {0.f, 0.f};

    const uint32_t* kp = g_kph + ((size_t)b * NTILE + sp * TPS) * 2048;
    const uint32_t* vp = g_vph + ((size_t)b * NTILE + sp * TPS) * 2048;

    #pragma unroll
    for (int r = 0; r < 4; r++) {
        int i = tid + 128 * r;
        cp16(smK + i * 16, kp + i * 4);
        cp16(smV + i * 16, vp + i * 4);
    }
    cp_commit();

    for (int kt = 0; kt < TPS; kt++) {
        cp_wait0();
        __syncthreads();
        if (kt + 1 < TPS) {
            uint32_t nbb = (uint32_t)((kt + 1) & 1) * 8192u;
            const uint32_t* ksrc = kp + (size_t)(kt + 1) * 2048;
            const uint32_t* vsrc = vp + (size_t)(kt + 1) * 2048;
            #pragma unroll
            for (int r = 0; r < 4; r++) {
                int i = tid + 128 * r;
                cp16(smK + nbb + i * 16, ksrc + i * 4);
                cp16(smV + nbb + i * 16, vsrc + i * 4);
            }
            cp_commit();
        }

        const uint4* Kp4 = (const uint4*)(Kb + (kt & 1) * 2048);
        const uint4* Vp4 = (const uint4*)(Vb + (kt & 1) * 2048);

        // ---- MMA1: S = Q K^T ----
        float sf[2][8][4];
        #pragma unroll
        for (int m = 0; m < 2; m++)
            #pragma unroll
            for (int t = 0; t < 8; t++)
                #pragma unroll
                for (int c = 0; c < 4; c++) sf[m][t][c] = 0.f;

        #pragma unroll
        for (int s = 0; s < 4; s++)
            #pragma unroll
            for (int tp = 0; tp < 4; tp++) {
                uint4 kb = Kp4[(s * 4 + tp) * 32 + lam];
                mma16(sf[0][2 * tp],     qa[0][s], kb.x, kb.y);
                mma16(sf[0][2 * tp + 1], qa[0][s], kb.z, kb.w);
                mma16(sf[1][2 * tp],     qa[1][s], kb.x, kb.y);
                mma16(sf[1][2 * tp + 1], qa[1][s], kb.z, kb.w);
            }

        // ---- softmax ----
        float rs[2][2] = {{0.f, 0.f}, {0.f, 0.f}};
        #pragma unroll
        for (int m = 0; m < 2; m++)
            #pragma unroll
            for (int t = 0; t < 8; t++) {
                float e0 = ex2(sf[m][t][0] * SC);
                float e1 = ex2(sf[m][t][1] * SC);
                float e2 = ex2(sf[m][t][2] * SC);
                float e3 = ex2(sf[m][t][3] * SC);
                rs[m][0] += e0 + e1;
                rs[m][1] += e2 + e3;
                sf[m][t][0] = e0; sf[m][t][1] = e1;
                sf[m][t][2] = e2; sf[m][t][3] = e3;
            }
        #pragma unroll
        for (int m = 0; m < 2; m++) {
            float a = rs[m][0], bs = rs[m][1];
            a += __shfl_xor_sync(0xffffffffu, a, 1);
            a += __shfl_xor_sync(0xffffffffu, a, 2);
            bs += __shfl_xor_sync(0xffffffffu, bs, 1);
            bs += __shfl_xor_sync(0xffffffffu, bs, 2);
            lA[m] += a;
            lB[m] += bs;
        }

        // P A-fragments: pure cvt
        uint32_t pa[2][4][4];
        #pragma unroll
        for (int m = 0; m < 2; m++)
            #pragma unroll
            for (int s = 0; s < 4; s++) {
                pa[m][s][0] = h2(sf[m][2 * s][0],     sf[m][2 * s][1]);
                pa[m][s][1] = h2(sf[m][2 * s][2],     sf[m][2 * s][3]);
                pa[m][s][2] = h2(sf[m][2 * s + 1][0], sf[m][2 * s + 1][1]);
                pa[m][s][3] = h2(sf[m][2 * s + 1][2], sf[m][2 * s + 1][3]);
            }

        // ---- MMA2: O += P V ----
        #pragma unroll
        for (int s = 0; s < 4; s++)
            #pragma unroll
            for (int tp = 0; tp < 4; tp++) {
                uint4 vb = Vp4[(s * 4 + tp) * 32 + lam];
                mma16(of[0][2 * tp],     pa[0][s], vb.x, vb.y);
                mma16(of[0][2 * tp + 1], pa[0][s], vb.z, vb.w);
                mma16(of[1][2 * tp],     pa[1][s], vb.x, vb.y);
                mma16(of[1][2 * tp + 1], pa[1][s], vb.z, vb.w);
            }
    }

    // ---- epilogue ----
    float* po = g_po + (size_t)(sp * BB + b) * CC * NN;
    float* pl = g_pl + (size_t)(sp * BB + b) * NN;
    #pragma unroll
    for (int m = 0; m < 2; m++)
        #pragma unroll
        for (int t = 0; t < 8; t++) {
            int rowa = q0 + w * 32 + m * 16 + g;
            int col = 8 * t + 2 * tau;
            po[(size_t)col       * NN + rowa]     = of[m][t][0];
            po[(size_t)(col + 1) * NN + rowa]     = of[m][t][1];
            po[(size_t)col       * NN + rowa + 8] = of[m][t][2];
            po[(size_t)(col + 1) * NN + rowa + 8] = of[m][t][3];
        }
    if (tau == 0) {
        #pragma unroll
        for (int m = 0; m < 2; m++) {
            int rowa = q0 + w * 32 + m * 16 + g;
            pl[rowa]     = lA[m];
            pl[rowa + 8] = lB[m];
        }
    }
}

// ---------------------------------------------------------------------------
// Kernel 3: combine partials: out = (O0 + O1) / (l0 + l1)
// ---------------------------------------------------------------------------
__global__ void __launch_bounds__(256) combine_kernel(float* __restrict__ out)
{
    int idx = blockIdx.x * 256 + threadIdx.x;
    int n = (idx * 4) & (NN - 1);
    int b = (idx * 4) >> 18;
    float4 a = ((const float4*)g_po)[idx];
    float4 c = ((const float4*)g_po)[BB * CC * NN / 4 + idx];
    const float* l0 = g_pl + (size_t)b * NN + n;
    const float* l1 = g_pl + (size_t)(BB + b) * NN + n;
    float4 o;
    o.x = (a.x + c.x) / (l0[0] + l1[0]);
    o.y = (a.y + c.y) / (l0[1] + l1[1]);
    o.z = (a.z + c.z) / (l0[2] + l1[2]);
    o.w = (a.w + c.w) / (l0[3] + l1[3]);
    ((float4*)out)[idx] = o;
}

// ---------------------------------------------------------------------------
extern "C" void kernel_launch(void* const* d_in, const int* in_sizes, int n_in,
                              void* d_out, int out_size)
{
    const float* x  = (const float*)d_in[0];
    const float* wq = (const float*)d_in[1];
    const float* bq = (const float*)d_in[2];
    const float* wk = (const float*)d_in[3];
    const float* bk = (const float*)d_in[4];
    const float* wv = (const float*)d_in[5];
    const float* bv = (const float*)d_in[6];
    float* out = (float*)d_out;

    const int smem_proj = 8192 * sizeof(uint32_t);          // 32768 B
    const int smem_attn = (4096 + 4096) * sizeof(uint32_t); // 32768 B
    cudaFuncSetAttribute(proj_kernel, cudaFuncAttributeMaxDynamicSharedMemorySize, smem_proj);
    cudaFuncSetAttribute(attn_mma_kernel, cudaFuncAttributeMaxDynamicSharedMemorySize, smem_attn);

    wpack_kernel<<<48, 256>>>(wq, wk, wv);
    dim3 gp(NN / 64, BB);
    proj_kernel<<<gp, 128, smem_proj>>>(x, bq, bk, bv);
    dim3 ga(NN / TQa, BB, NSPLIT);
    attn_mma_kernel<<<ga, 128, smem_attn>>>();
    combine_kernel<<<BB * CC * NN / 4 / 256, 256>>>(out);
}